// round 8
// baseline (speedup 1.0000x reference)
#include <cuda_runtime.h>

#define BATCH 8
#define NN    32

__device__ float gPart[BATCH][16][32];   // per (b, i-pair, f)
__device__ unsigned int gCount = 0;

typedef unsigned long long u64;

__device__ __forceinline__ u64 pk2(float lo, float hi) {
    u64 r; asm("mov.b64 %0, {%1, %2};" : "=l"(r) : "f"(lo), "f"(hi)); return r;
}
__device__ __forceinline__ void upk2(u64 v, float& lo, float& hi) {
    asm("mov.b64 {%0, %1}, %2;" : "=f"(lo), "=f"(hi) : "l"(v));
}
__device__ __forceinline__ u64 fma2(u64 a, u64 b, u64 c) {
    u64 d; asm("fma.rn.f32x2 %0, %1, %2, %3;" : "=l"(d) : "l"(a), "l"(b), "l"(c)); return d;
}
__device__ __forceinline__ u64 mul2(u64 a, u64 b) {
    u64 d; asm("mul.rn.f32x2 %0, %1, %2;" : "=l"(d) : "l"(a), "l"(b)); return d;
}
// 16B-column permutation per row: {0,1,4,5} — separates rows 8/16/24 apart
__device__ __forceinline__ int swzperm(int o) {
    return (((o >> 4) & 1) << 2) | ((o >> 3) & 1);
}

#define DYN_FLOATS 4352

// ---------------- fused kernel: one block per (b, i-pair) ----------------
__global__ __launch_bounds__(256, 1) void fused_kernel(
    const float* __restrict__ x,  const float* __restrict__ W1, const float* __restrict__ b1,
    const float* __restrict__ W2, const float* __restrict__ b2,
    const float* __restrict__ eq, const float* __restrict__ eqb,
    const float* __restrict__ fc_w, const float* __restrict__ fc_b,
    const float* __restrict__ out_w, const float* __restrict__ out_b,
    float* __restrict__ out)
{
    const int b = blockIdx.x >> 4, ip = blockIdx.x & 15;
    const int t = threadIdx.x;

    // persistent static shared (~21 KB)
    __shared__ __align__(16) float As_[1024];    // A[d][k]
    __shared__ __align__(16) float PsM[1024];    // P[d][o] (per current i)
    __shared__ __align__(16) float Rk_[1024];    // Rk[o][k] (per current i)
    __shared__ __align__(16) float BaseT[1024];  // BaseT[j][o] (per current i)
    __shared__ __align__(16) float Fwm[1024];    // fc_w swizzled [o][c16^perm]
    __shared__ float Sd[32], S2d[32], Csd[32], BiC[32], fbv[32], Ai[2][32];
    __shared__ unsigned int isLast;

    // dynamic shared: 4352 floats = 17.4 KB (total ~38.5 KB < 48 KB)
    extern __shared__ __align__(16) float dyn[];

    // phase A-C overlay
    float* W2S = dyn;           // [32][33]
    float* h1  = dyn + 1056;    // [32][33]
    float* xS  = dyn + 2112;    // 512
    float* W1S = dyn + 2624;    // 512

    // ---- phase A: stage small tensors ----
    for (int c = t; c < 512; c += 256) { xS[c] = x[b * 512 + c]; W1S[c] = W1[c]; }
    for (int c = t; c < 1024; c += 256) {
        W2S[(c & 31) * 33 + (c >> 5)] = W2[c];
        int o = c >> 5, f = c & 31;
        Fwm[o * 32 + ((((f >> 2) ^ swzperm(o)) << 2) | (f & 3))] = fc_w[c];
    }
    if (t < 32) fbv[t] = fc_b[t];
    __syncthreads();

    // ---- phase B: h1 = relu(x @ W1 + b1) ----
    for (int c = t; c < 1024; c += 256) {
        int ii = c >> 5, d = c & 31;
        float acc = b1[d];
        #pragma unroll
        for (int e = 0; e < 16; e++) acc = fmaf(xS[ii * 16 + e], W1S[e * 32 + d], acc);
        h1[ii * 33 + d] = fmaxf(acc, 0.0f);
    }
    __syncthreads();

    // ---- phase C: As[d][ii] = relu(h1 @ W2 + b2), transposed ----
    for (int c = t; c < 1024; c += 256) {
        int d = c >> 5, ii = c & 31;
        float acc = b2[d];
        #pragma unroll
        for (int e = 0; e < 32; e++) acc = fmaf(h1[ii * 33 + e], W2S[d * 33 + e], acc);
        As_[d * 32 + ii] = fmaxf(acc, 0.0f);
    }
    __syncthreads();

    // ---- phase D: per-d stats + both Ai ----
    if (t < 32) {
        Ai[0][t] = As_[t * 32 + ip * 2];
        Ai[1][t] = As_[t * 32 + ip * 2 + 1];
    }
    {
        int d = t >> 3, r = t & 7;
        float s = 0.0f, cs = 0.0f;
        #pragma unroll
        for (int q = 0; q < 4; q++) {
            float a = As_[d * 32 + r * 4 + q];
            s += a; cs += a * a * a;
        }
        #pragma unroll
        for (int off = 4; off; off >>= 1) {
            s  += __shfl_down_sync(0xffffffffu, s,  off, 8);
            cs += __shfl_down_sync(0xffffffffu, cs, off, 8);
        }
        if (r == 0) { Sd[d] = s; S2d[d] = s * s; Csd[d] = cs; }
    }
    __syncthreads();

    // ---- main-loop thread mappings ----
    const int jg = t >> 6, s = t & 63;
    const int k0 = (s & 7) * 4, o0 = (s >> 3) * 4;      // GEMM1: 4o x 4k
    const int l = t & 31, w2 = (t >> 5) & 1;
    const int p = w2 * 8 + (l & 7);                      // GEMM2 tile pos 0..15
    const int f0 = (p >> 2) * 8;                         // {0,8,16,24}
    const int kb16 = (p & 3) * 2;                        // logical col16 base
    const int oq4 = l >> 3;                              // in-warp o-quarter 0..3
    const int ob = oq4 * 8;
    float* Yg = dyn + jg * 1024;
    const int barid = 1 + jg;

    float accF[8];
    #pragma unroll
    for (int q = 0; q < 8; q++) accF[q] = 0.0f;

    // ================= per-i passes =================
    #pragma unroll 1
    for (int ii = 0; ii < 2; ii++) {
        float* QmR = dyn;
        float* PsR = dyn + 1024;
        float* QmB = dyn + 2048;
        float* PsB = dyn + 3072;
        float* Cn8 = dyn + 4096;   // 256

        // ---- phase E: single-pass eq fold for this i ----
        {
            float cnp = 0.0f;
            #pragma unroll
            for (int q = 0; q < 4; q++) {
                const int c = t + q * 256;
                const int d = c >> 5;
                const float* e = eq + (size_t)c * 12;
                float4 e03  = *(const float4*)(e);
                float4 e47  = *(const float4*)(e + 4);
                float4 e811 = *(const float4*)(e + 8);
                float ai = Ai[ii][d], sv = Sd[d], s2 = S2d[d];
                PsM[c] = fmaf(e03.x, ai, e03.y * sv);
                QmR[c] = fmaf(sv * e03.z, ai, e47.x * s2);
                PsR[c] = e811.z;   // e10
                QmB[c] = fmaf(sv * e03.w, ai, e47.y * s2);
                PsB[c] = e811.y;   // e9
                cnp += fmaf(e47.z, s2 * ai, fmaf(e811.x, ai * ai * ai,
                       fmaf(e47.w, s2 * sv, e811.w * Csd[d])));
            }
            Cn8[(t >> 5) * 32 + (t & 31)] = cnp;
        }
        __syncthreads();

        // ---- phase F: Rk[o][k] (cube inline) + BiC ----
        {
            const int o = t >> 3, kq = (t & 7) * 4;
            u64 acc0 = 0ull, acc1 = 0ull;
            #pragma unroll
            for (int d = 0; d < 32; d++) {
                float qv = QmR[d * 32 + o], pv = PsR[d * 32 + o];
                u64 qm = pk2(qv, qv), ps = pk2(pv, pv);
                ulonglong2 as2 = *(const ulonglong2*)&As_[d * 32 + kq];
                u64 a3x = mul2(mul2(as2.x, as2.x), as2.x);
                u64 a3y = mul2(mul2(as2.y, as2.y), as2.y);
                acc0 = fma2(qm, as2.x, fma2(ps, a3x, acc0));
                acc1 = fma2(qm, as2.y, fma2(ps, a3y, acc1));
            }
            float v0, v1, v2, v3;
            upk2(acc0, v0, v1); upk2(acc1, v2, v3);
            *(float4*)&Rk_[o * 32 + kq] = make_float4(v0, v1, v2, v3);
        }
        if (t < 32) {
            float acc = eqb[t];
            #pragma unroll
            for (int w = 0; w < 8; w++) acc += Cn8[w * 32 + t];
            BiC[t] = acc;
        }
        __syncthreads();

        // ---- phase G: BaseT[j][o] (cube inline) ----
        {
            const int j = t >> 3, oq = (t & 7) * 4;
            u64 acc0 = 0ull, acc1 = 0ull;
            #pragma unroll
            for (int d = 0; d < 32; d++) {
                float ajv = As_[d * 32 + j];
                float a3v = ajv * ajv * ajv;
                u64 ajb = pk2(ajv, ajv), a3b = pk2(a3v, a3v);
                ulonglong2 qm2 = *(const ulonglong2*)&QmB[d * 32 + oq];
                ulonglong2 ps2 = *(const ulonglong2*)&PsB[d * 32 + oq];
                acc0 = fma2(qm2.x, ajb, fma2(ps2.x, a3b, acc0));
                acc1 = fma2(qm2.y, ajb, fma2(ps2.y, a3b, acc1));
            }
            float v0, v1, v2, v3;
            upk2(acc0, v0, v1); upk2(acc1, v2, v3);
            float4 bc = *(const float4*)&BiC[oq];
            *(float4*)&BaseT[j * 32 + oq] =
                make_float4(v0 + bc.x, v1 + bc.y, v2 + bc.z, v3 + bc.w);
        }
        __syncthreads();

        // ---- main: 4 j-pairs per group ----
        #pragma unroll 1
        for (int jb = 0; jb < 4; jb++) {
            const int j0 = jb * 8 + jg * 2;

            // GEMM1 for both j
            u64 yA[4][2], yB[4][2];
            {
                float4 bA = *(const float4*)&BaseT[j0 * 32 + o0];
                float4 bB = *(const float4*)&BaseT[(j0 + 1) * 32 + o0];
                float aA[4] = { bA.x, bA.y, bA.z, bA.w };
                float aB[4] = { bB.x, bB.y, bB.z, bB.w };
                #pragma unroll
                for (int oi = 0; oi < 4; oi++) {
                    float4 r = *(const float4*)&Rk_[(o0 + oi) * 32 + k0];
                    yA[oi][0] = pk2(r.x + aA[oi], r.y + aA[oi]);
                    yA[oi][1] = pk2(r.z + aA[oi], r.w + aA[oi]);
                    yB[oi][0] = pk2(r.x + aB[oi], r.y + aB[oi]);
                    yB[oi][1] = pk2(r.z + aB[oi], r.w + aB[oi]);
                }
            }
            #pragma unroll
            for (int d = 0; d < 32; d++) {
                float2 ajp = *(const float2*)&As_[d * 32 + j0];
                ulonglong2 a2 = *(const ulonglong2*)&As_[d * 32 + k0];
                u64 ajA = pk2(ajp.x, ajp.x);
                u64 ajB = pk2(ajp.y, ajp.y);
                u64 sA01 = mul2(a2.x, ajA), sA23 = mul2(a2.y, ajA);
                u64 sB01 = mul2(a2.x, ajB), sB23 = mul2(a2.y, ajB);
                float4 p4 = *(const float4*)&PsM[d * 32 + o0];
                u64 pd;
                pd = pk2(p4.x, p4.x);
                yA[0][0] = fma2(pd, sA01, yA[0][0]); yA[0][1] = fma2(pd, sA23, yA[0][1]);
                yB[0][0] = fma2(pd, sB01, yB[0][0]); yB[0][1] = fma2(pd, sB23, yB[0][1]);
                pd = pk2(p4.y, p4.y);
                yA[1][0] = fma2(pd, sA01, yA[1][0]); yA[1][1] = fma2(pd, sA23, yA[1][1]);
                yB[1][0] = fma2(pd, sB01, yB[1][0]); yB[1][1] = fma2(pd, sB23, yB[1][1]);
                pd = pk2(p4.z, p4.z);
                yA[2][0] = fma2(pd, sA01, yA[2][0]); yA[2][1] = fma2(pd, sA23, yA[2][1]);
                yB[2][0] = fma2(pd, sB01, yB[2][0]); yB[2][1] = fma2(pd, sB23, yB[2][1]);
                pd = pk2(p4.w, p4.w);
                yA[3][0] = fma2(pd, sA01, yA[3][0]); yA[3][1] = fma2(pd, sA23, yA[3][1]);
                yB[3][0] = fma2(pd, sB01, yB[3][0]); yB[3][1] = fma2(pd, sB23, yB[3][1]);
            }

            // two halves: store swizzled tile -> bar -> GEMM2 (4-way o-split) -> bar
            #pragma unroll
            for (int half = 0; half < 2; half++) {
                u64 (*yy)[2] = half ? yB : yA;

                #pragma unroll
                for (int oi = 0; oi < 4; oi++) {
                    float v0, v1, v2, v3;
                    upk2(yy[oi][0], v0, v1); upk2(yy[oi][1], v2, v3);
                    float4 v;
                    v.x = fmaxf(v0, 0.f); v.y = fmaxf(v1, 0.f);
                    v.z = fmaxf(v2, 0.f); v.w = fmaxf(v3, 0.f);
                    const int o = o0 + oi;
                    *(float4*)&Yg[o * 32 + (((k0 >> 2) ^ swzperm(o)) << 2)] = v;
                }
                asm volatile("bar.sync %0, %1;" :: "r"(barid), "r"(64) : "memory");

                // GEMM2: z[8f][8k] over my 8-o quarter
                u64 z[8][4];
                #pragma unroll
                for (int fi = 0; fi < 8; fi++) {
                    z[fi][0] = 0ull; z[fi][1] = 0ull; z[fi][2] = 0ull; z[fi][3] = 0ull;
                }
                #pragma unroll
                for (int oo = 0; oo < 8; oo++) {
                    const int o = ob + oo;
                    const int pm = swzperm(o);
                    float4 wa = *(const float4*)&Fwm[o * 32 + (((f0 >> 2) ^ pm) << 2)];
                    float4 wb = *(const float4*)&Fwm[o * 32 + ((((f0 >> 2) + 1) ^ pm) << 2)];
                    ulonglong2 y0 = *(const ulonglong2*)&Yg[o * 32 + ((kb16 ^ pm) << 2)];
                    ulonglong2 y1 = *(const ulonglong2*)&Yg[o * 32 + (((kb16 + 1) ^ pm) << 2)];
                    float wv[8] = { wa.x, wa.y, wa.z, wa.w, wb.x, wb.y, wb.z, wb.w };
                    #pragma unroll
                    for (int fi = 0; fi < 8; fi++) {
                        u64 wd = pk2(wv[fi], wv[fi]);
                        z[fi][0] = fma2(wd, y0.x, z[fi][0]);
                        z[fi][1] = fma2(wd, y0.y, z[fi][1]);
                        z[fi][2] = fma2(wd, y1.x, z[fi][2]);
                        z[fi][3] = fma2(wd, y1.y, z[fi][3]);
                    }
                }
                // combine 4 o-quarters (xor8, xor16), relu, keep own quarter's k-pair
                #pragma unroll
                for (int fi = 0; fi < 8; fi++) {
                    const float fb_ = fbv[f0 + fi];
                    #pragma unroll
                    for (int q = 0; q < 4; q++) {
                        float a0, a1;
                        upk2(z[fi][q], a0, a1);
                        a0 += __shfl_xor_sync(0xffffffffu, a0, 8);
                        a0 += __shfl_xor_sync(0xffffffffu, a0, 16);
                        a1 += __shfl_xor_sync(0xffffffffu, a1, 8);
                        a1 += __shfl_xor_sync(0xffffffffu, a1, 16);
                        if (q == oq4)
                            accF[fi] += fmaxf(a0 + fb_, 0.0f) + fmaxf(a1 + fb_, 0.0f);
                    }
                }
                asm volatile("bar.sync %0, %1;" :: "r"(barid), "r"(64) : "memory");
            }
        }
        __syncthreads();   // Yg dead before next ii's EFG reuses dyn
    }

    // ---- deterministic block reduction ----
    float* Prt = dyn;
    *(float4*)&Prt[t * 8]     = make_float4(accF[0], accF[1], accF[2], accF[3]);
    *(float4*)&Prt[t * 8 + 4] = make_float4(accF[4], accF[5], accF[6], accF[7]);
    __syncthreads();
    if (t < 32) {
        const int f = t, a = f >> 3;
        float acc = 0.0f;
        #pragma unroll
        for (int g = 0; g < 4; g++)
            #pragma unroll
            for (int jsub = 0; jsub < 4; jsub++)
                #pragma unroll
                for (int q = 0; q < 4; q++) {
                    int tt = g * 64 + (a >> 1) * 32 + q * 8 + ((a & 1) * 4 + jsub);
                    acc += Prt[tt * 8 + (f & 7)];
                }
        gPart[b][ip][f] = acc;
    }
    __threadfence();
    __syncthreads();

    // ---- last block performs the final head ----
    if (t == 0) {
        unsigned int old = atomicAdd(&gCount, 1u);
        isLast = (old == 127u) ? 1u : 0u;
    }
    __syncthreads();
    if (isLast) {
        __threadfence();
        const int bb = t >> 5, oo = t & 31;
        float acc = 0.0f;
        #pragma unroll
        for (int pp = 0; pp < 16; pp++) acc += gPart[bb][pp][oo];
        float v = fmaxf(acc, 0.0f) * out_w[oo];
        #pragma unroll
        for (int off = 16; off; off >>= 1) v += __shfl_down_sync(0xffffffffu, v, off);
        if (oo == 0) out[bb] = v + out_b[0];
        __syncthreads();
        if (t == 0) gCount = 0u;   // reset for next replay
    }
}

extern "C" void kernel_launch(void* const* d_in, const int* in_sizes, int n_in,
                              void* d_out, int out_size)
{
    const float* x    = (const float*)d_in[0];
    const float* W1   = (const float*)d_in[1];
    const float* b1   = (const float*)d_in[2];
    const float* W2   = (const float*)d_in[3];
    const float* b2   = (const float*)d_in[4];
    const float* eq   = (const float*)d_in[5];
    const float* eqb  = (const float*)d_in[6];
    const float* fcw  = (const float*)d_in[7];
    const float* fcb  = (const float*)d_in[8];
    const float* outw = (const float*)d_in[9];
    const float* outb = (const float*)d_in[10];
    float* out = (float*)d_out;

    fused_kernel<<<BATCH * 16, 256, DYN_FLOATS * sizeof(float)>>>(
        x, W1, b1, W2, b2, eq, eqb, fcw, fcb, outw, outb, out);
}

// round 9
// speedup vs baseline: 1.1428x; 1.1428x over previous
#include <cuda_runtime.h>

#define BATCH 8
#define NN    32

__device__ float gPart[BATCH][NN][32];
__device__ unsigned int gCount = 0;

typedef unsigned long long u64;

__device__ __forceinline__ u64 pk2(float lo, float hi) {
    u64 r; asm("mov.b64 %0, {%1, %2};" : "=l"(r) : "f"(lo), "f"(hi)); return r;
}
__device__ __forceinline__ void upk2(u64 v, float& lo, float& hi) {
    asm("mov.b64 {%0, %1}, %2;" : "=f"(lo), "=f"(hi) : "l"(v));
}
__device__ __forceinline__ u64 fma2(u64 a, u64 b, u64 c) {
    u64 d; asm("fma.rn.f32x2 %0, %1, %2, %3;" : "=l"(d) : "l"(a), "l"(b), "l"(c)); return d;
}
__device__ __forceinline__ u64 mul2(u64 a, u64 b) {
    u64 d; asm("mul.rn.f32x2 %0, %1, %2;" : "=l"(d) : "l"(a), "l"(b)); return d;
}

#define YSTRIDE 36          // Yg row stride (144 B: 16B-aligned, 4-word bank rotation per row)
#define FSTRIDE 36          // Fwm row stride (same rotation, so o-parity halves use disjoint banks)
#define YG_PER_GROUP 1152   // 32 * 36  (ONE j tile per group)
#define DYN_FLOATS 6144

// ---------------- fused kernel: one block per (b, i) ----------------
__global__ __launch_bounds__(256, 2) void fused_kernel(
    const float* __restrict__ x,  const float* __restrict__ W1, const float* __restrict__ b1,
    const float* __restrict__ W2, const float* __restrict__ b2,
    const float* __restrict__ eq, const float* __restrict__ eqb,
    const float* __restrict__ fc_w, const float* __restrict__ fc_b,
    const float* __restrict__ out_w, const float* __restrict__ out_b,
    float* __restrict__ out)
{
    const int b = blockIdx.x >> 5, i = blockIdx.x & 31;
    const int t = threadIdx.x;

    // persistent static shared (~21.3 KB)
    __shared__ __align__(16) float As_[1024];    // A[d][k]
    __shared__ __align__(16) float PsM[1024];    // P[d][o]
    __shared__ __align__(16) float Rk_[1024];    // Rk[o][k]
    __shared__ __align__(16) float BaseT[1024];  // BaseT[j][o]
    __shared__ __align__(16) float Fwm[1152];    // fc_w[o][f], stride 36
    __shared__ float Sd[32], S2d[32], Csd[32], BiC[32], fbv[32], Ai[32];
    __shared__ unsigned int isLast;

    // dynamic shared: 6144 floats = 24576 B; total smem ~46 KB < 48 KB default
    extern __shared__ __align__(16) float dyn[];

    // prologue overlay (phases A-C)
    float* W2S = dyn;           // [32][33]
    float* h1  = dyn + 1056;    // [32][33]
    float* xS  = dyn + 2112;    // 512
    float* W1S = dyn + 2624;    // 512
    // prologue overlay (phases D-G)
    float* A3  = dyn;           // 1024
    float* QmR = dyn + 1024;
    float* PsR = dyn + 2048;
    float* QmB = dyn + 3072;
    float* PsB = dyn + 4096;
    float* Cn  = dyn + 5120;
    // main loop: Yg per group at dyn + jg*YG_PER_GROUP; epilogue: Prt = dyn

    // ---- phase A: stage small tensors ----
    for (int c = t; c < 512; c += 256) { xS[c] = x[b * 512 + c]; W1S[c] = W1[c]; }
    for (int c = t; c < 1024; c += 256) {
        W2S[(c & 31) * 33 + (c >> 5)] = W2[c];
        Fwm[(c >> 5) * FSTRIDE + (c & 31)] = fc_w[c];
    }
    if (t < 32) fbv[t] = fc_b[t];
    __syncthreads();

    // ---- phase B: h1 = relu(x @ W1 + b1) ----
    for (int c = t; c < 1024; c += 256) {
        int ii = c >> 5, d = c & 31;
        float acc = b1[d];
        #pragma unroll
        for (int e = 0; e < 16; e++) acc = fmaf(xS[ii * 16 + e], W1S[e * 32 + d], acc);
        h1[ii * 33 + d] = fmaxf(acc, 0.0f);
    }
    __syncthreads();

    // ---- phase C: As[d][ii] = relu(h1 @ W2 + b2), transposed ----
    for (int c = t; c < 1024; c += 256) {
        int d = c >> 5, ii = c & 31;
        float acc = b2[d];
        #pragma unroll
        for (int e = 0; e < 32; e++) acc = fmaf(h1[ii * 33 + e], W2S[d * 33 + e], acc);
        As_[d * 32 + ii] = fmaxf(acc, 0.0f);
    }
    __syncthreads();

    // ---- phase D: A3, per-d stats, Ai ----
    if (t < 32) Ai[t] = As_[t * 32 + i];
    {
        int d = t >> 3, r = t & 7;
        float s = 0.0f, cs = 0.0f;
        #pragma unroll
        for (int q = 0; q < 4; q++) {
            float a = As_[d * 32 + r * 4 + q];
            float a3 = a * a * a;
            s += a; cs += a3;
            A3[d * 32 + r * 4 + q] = a3;
        }
        #pragma unroll
        for (int off = 4; off; off >>= 1) {
            s  += __shfl_down_sync(0xffffffffu, s,  off, 8);
            cs += __shfl_down_sync(0xffffffffu, cs, off, 8);
        }
        if (r == 0) { Sd[d] = s; S2d[d] = s * s; Csd[d] = cs; }
    }
    __syncthreads();

    // ---- phase E: single-pass eq fold ----
    for (int c = t; c < 1024; c += 256) {
        int d = c >> 5;
        const float* e = eq + (size_t)c * 12;
        float4 e03  = *(const float4*)(e);
        float4 e47  = *(const float4*)(e + 4);
        float4 e811 = *(const float4*)(e + 8);
        float ai = Ai[d], s = Sd[d], s2 = S2d[d];
        PsM[c] = fmaf(e03.x, ai, e03.y * s);
        QmR[c] = fmaf(s * e03.z, ai, e47.x * s2);
        PsR[c] = e811.z;   // e10
        QmB[c] = fmaf(s * e03.w, ai, e47.y * s2);
        PsB[c] = e811.y;   // e9
        Cn[c]  = fmaf(e47.z, s2 * ai, fmaf(e811.x, ai * ai * ai,
                 fmaf(e47.w, s2 * s, e811.w * Csd[d])));
    }
    __syncthreads();

    // ---- phase F (vectorized): Rk[o][k] ----
    {
        const int o = t >> 3, kq = (t & 7) * 4;
        u64 acc0 = 0ull, acc1 = 0ull;
        #pragma unroll
        for (int d = 0; d < 32; d++) {
            float qv = QmR[d * 32 + o], pv = PsR[d * 32 + o];
            u64 qm = pk2(qv, qv), ps = pk2(pv, pv);
            ulonglong2 as2 = *(const ulonglong2*)&As_[d * 32 + kq];
            ulonglong2 a32 = *(const ulonglong2*)&A3[d * 32 + kq];
            acc0 = fma2(qm, as2.x, fma2(ps, a32.x, acc0));
            acc1 = fma2(qm, as2.y, fma2(ps, a32.y, acc1));
        }
        float v0, v1, v2, v3;
        upk2(acc0, v0, v1); upk2(acc1, v2, v3);
        *(float4*)&Rk_[o * 32 + kq] = make_float4(v0, v1, v2, v3);
    }
    if (t < 32) {
        float acc = eqb[t];
        #pragma unroll
        for (int d = 0; d < 32; d++) acc += Cn[d * 32 + t];
        BiC[t] = acc;
    }
    __syncthreads();

    // ---- phase G (vectorized): BaseT[j][o] ----
    {
        const int j = t >> 3, oq = (t & 7) * 4;
        u64 acc0 = 0ull, acc1 = 0ull;
        #pragma unroll
        for (int d = 0; d < 32; d++) {
            float ajv = As_[d * 32 + j], a3v = A3[d * 32 + j];
            u64 ajb = pk2(ajv, ajv), a3b = pk2(a3v, a3v);
            ulonglong2 qm2 = *(const ulonglong2*)&QmB[d * 32 + oq];
            ulonglong2 ps2 = *(const ulonglong2*)&PsB[d * 32 + oq];
            acc0 = fma2(qm2.x, ajb, fma2(ps2.x, a3b, acc0));
            acc1 = fma2(qm2.y, ajb, fma2(ps2.y, a3b, acc1));
        }
        float v0, v1, v2, v3;
        upk2(acc0, v0, v1); upk2(acc1, v2, v3);
        float4 bc = *(const float4*)&BiC[oq];
        *(float4*)&BaseT[j * 32 + oq] =
            make_float4(v0 + bc.x, v1 + bc.y, v2 + bc.z, v3 + bc.w);
    }
    __syncthreads();

    // ================= main loop: 4 groups of 64 threads, j-pair per pass =================
    const int jg = t >> 6;
    const int s  = t & 63;
    // GEMM1 mapping (4o x 4k per thread, per j)
    const int k0 = (s & 7) * 4, o0 = (s >> 3) * 4;
    // GEMM2 mapping: 8f x 4k per tile, o-PARITY split across (l ^ 16)
    const int w2 = s >> 5;
    const int l  = t & 31;
    const int oh = l >> 4;               // 0: even o, 1: odd o
    const int tileid = w2 * 16 + (l & 15);
    const int f0 = (tileid >> 3) * 8;
    const int kb = (tileid & 7) * 4;
    float* Yg = dyn + jg * YG_PER_GROUP;
    const int barid = 1 + jg;

    float accF[8];
    #pragma unroll
    for (int q = 0; q < 8; q++) accF[q] = 0.0f;

    #pragma unroll 1
    for (int jb = 0; jb < 4; jb++) {
        const int j0 = jb * 8 + jg * 2;     // j1 = j0 + 1

        // ---- GEMM1 for both j (register reuse of As/Ps) ----
        u64 yA[4][2], yB[4][2];
        {
            float4 bA = *(const float4*)&BaseT[j0 * 32 + o0];
            float4 bB = *(const float4*)&BaseT[(j0 + 1) * 32 + o0];
            float aA[4] = { bA.x, bA.y, bA.z, bA.w };
            float aB[4] = { bB.x, bB.y, bB.z, bB.w };
            #pragma unroll
            for (int oi = 0; oi < 4; oi++) {
                float4 r = *(const float4*)&Rk_[(o0 + oi) * 32 + k0];
                yA[oi][0] = pk2(r.x + aA[oi], r.y + aA[oi]);
                yA[oi][1] = pk2(r.z + aA[oi], r.w + aA[oi]);
                yB[oi][0] = pk2(r.x + aB[oi], r.y + aB[oi]);
                yB[oi][1] = pk2(r.z + aB[oi], r.w + aB[oi]);
            }
        }
        #pragma unroll
        for (int d = 0; d < 32; d++) {
            float2 ajp = *(const float2*)&As_[d * 32 + j0];
            ulonglong2 a2 = *(const ulonglong2*)&As_[d * 32 + k0];
            u64 ajA = pk2(ajp.x, ajp.x);
            u64 ajB = pk2(ajp.y, ajp.y);
            u64 sA01 = mul2(a2.x, ajA), sA23 = mul2(a2.y, ajA);
            u64 sB01 = mul2(a2.x, ajB), sB23 = mul2(a2.y, ajB);
            float4 p4 = *(const float4*)&PsM[d * 32 + o0];
            u64 pd;
            pd = pk2(p4.x, p4.x);
            yA[0][0] = fma2(pd, sA01, yA[0][0]); yA[0][1] = fma2(pd, sA23, yA[0][1]);
            yB[0][0] = fma2(pd, sB01, yB[0][0]); yB[0][1] = fma2(pd, sB23, yB[0][1]);
            pd = pk2(p4.y, p4.y);
            yA[1][0] = fma2(pd, sA01, yA[1][0]); yA[1][1] = fma2(pd, sA23, yA[1][1]);
            yB[1][0] = fma2(pd, sB01, yB[1][0]); yB[1][1] = fma2(pd, sB23, yB[1][1]);
            pd = pk2(p4.z, p4.z);
            yA[2][0] = fma2(pd, sA01, yA[2][0]); yA[2][1] = fma2(pd, sA23, yA[2][1]);
            yB[2][0] = fma2(pd, sB01, yB[2][0]); yB[2][1] = fma2(pd, sB23, yB[2][1]);
            pd = pk2(p4.w, p4.w);
            yA[3][0] = fma2(pd, sA01, yA[3][0]); yA[3][1] = fma2(pd, sA23, yA[3][1]);
            yB[3][0] = fma2(pd, sB01, yB[3][0]); yB[3][1] = fma2(pd, sB23, yB[3][1]);
        }

        // ---- two halves: store tile -> bar -> GEMM2 -> bar ----
        #pragma unroll
        for (int half = 0; half < 2; half++) {
            u64 (*yy)[2] = half ? yB : yA;

            #pragma unroll
            for (int oi = 0; oi < 4; oi++) {
                float v0, v1, v2, v3;
                upk2(yy[oi][0], v0, v1); upk2(yy[oi][1], v2, v3);
                float4 v;
                v.x = fmaxf(v0, 0.f); v.y = fmaxf(v1, 0.f);
                v.z = fmaxf(v2, 0.f); v.w = fmaxf(v3, 0.f);
                *(float4*)&Yg[(o0 + oi) * YSTRIDE + k0] = v;
            }
            asm volatile("bar.sync %0, %1;" :: "r"(barid), "r"(64) : "memory");

            // GEMM2: z[f,k] partial over my o-parity class, then shfl-combine with lane^16
            u64 z[8][2];
            #pragma unroll
            for (int fi = 0; fi < 8; fi++) { z[fi][0] = 0ull; z[fi][1] = 0ull; }
            #pragma unroll
            for (int oo = 0; oo < 16; oo++) {
                const int o = (oo << 1) + oh;       // parity split: rows 1 apart -> disjoint banks
                float4 wa = *(const float4*)&Fwm[o * FSTRIDE + f0];
                float4 wb = *(const float4*)&Fwm[o * FSTRIDE + f0 + 4];
                ulonglong2 ya = *(const ulonglong2*)&Yg[o * YSTRIDE + kb];
                float wv[8] = { wa.x, wa.y, wa.z, wa.w, wb.x, wb.y, wb.z, wb.w };
                #pragma unroll
                for (int fi = 0; fi < 8; fi++) {
                    u64 wd = pk2(wv[fi], wv[fi]);
                    z[fi][0] = fma2(wd, ya.x, z[fi][0]);
                    z[fi][1] = fma2(wd, ya.y, z[fi][1]);
                }
            }
            #pragma unroll
            for (int fi = 0; fi < 8; fi++) {
                const float fb_ = fbv[f0 + fi];
                #pragma unroll
                for (int idx = 0; idx < 2; idx++) {
                    float a0, a1;
                    upk2(z[fi][idx], a0, a1);
                    a0 += __shfl_xor_sync(0xffffffffu, a0, 16);
                    a1 += __shfl_xor_sync(0xffffffffu, a1, 16);
                    if (idx == oh)
                        accF[fi] += fmaxf(a0 + fb_, 0.0f) + fmaxf(a1 + fb_, 0.0f);
                }
            }
            asm volatile("bar.sync %0, %1;" :: "r"(barid), "r"(64) : "memory");
        }
    }

    // ---- deterministic block reduction (Prt aliases dyn) ----
    __syncthreads();
    float* Prt = dyn;
    #pragma unroll
    for (int q = 0; q < 8; q += 4)
        *(float4*)&Prt[t * 8 + q] = make_float4(accF[q], accF[q+1], accF[q+2], accF[q+3]);
    __syncthreads();
    if (t < 32) {
        const int f = t;
        const int fg = f >> 3, fi = f & 7;
        float acc = 0.0f;
        #pragma unroll
        for (int g = 0; g < 4; g++)
            #pragma unroll
            for (int ohh = 0; ohh < 2; ohh++)
                #pragma unroll
                for (int r = 0; r < 8; r++)
                    acc += Prt[(g * 64 + (fg >> 1) * 32 + ohh * 16 + (fg & 1) * 8 + r) * 8 + fi];
        gPart[b][i][f] = acc;
    }
    __threadfence();
    __syncthreads();

    // ---- last block performs the final head ----
    if (t == 0) {
        unsigned int old = atomicAdd(&gCount, 1u);
        isLast = (old == (unsigned)(BATCH * NN - 1)) ? 1u : 0u;
    }
    __syncthreads();
    if (isLast) {
        __threadfence();
        const int bb = t >> 5, oo = t & 31;
        float acc = 0.0f;
        #pragma unroll
        for (int ii = 0; ii < NN; ii++) acc += gPart[bb][ii][oo];
        float v = fmaxf(acc, 0.0f) * out_w[oo];
        #pragma unroll
        for (int off = 16; off; off >>= 1) v += __shfl_down_sync(0xffffffffu, v, off);
        if (oo == 0) out[bb] = v + out_b[0];
        __syncthreads();
        if (t == 0) gCount = 0u;   // reset for next replay
    }
}

extern "C" void kernel_launch(void* const* d_in, const int* in_sizes, int n_in,
                              void* d_out, int out_size)
{
    const float* x    = (const float*)d_in[0];
    const float* W1   = (const float*)d_in[1];
    const float* b1   = (const float*)d_in[2];
    const float* W2   = (const float*)d_in[3];
    const float* b2   = (const float*)d_in[4];
    const float* eq   = (const float*)d_in[5];
    const float* eqb  = (const float*)d_in[6];
    const float* fcw  = (const float*)d_in[7];
    const float* fcb  = (const float*)d_in[8];
    const float* outw = (const float*)d_in[9];
    const float* outb = (const float*)d_in[10];
    float* out = (float*)d_out;

    fused_kernel<<<BATCH * NN, 256, DYN_FLOATS * sizeof(float)>>>(
        x, W1, b1, W2, b2, eq, eqb, fcw, fcb, outw, outb, out);
}